// round 5
// baseline (speedup 1.0000x reference)
#include <cuda_runtime.h>
#include <math.h>

#define BATCH 2048
#define SEQ   128
#define HID   512
#define TOUT  24
#define MR    14     // batch rows per CTA (147 CTAs -> 147 of 148 SMs)
#define MRP   16     // padded row length (floats) for vector LDS
#define NACC  7      // u64 accumulators per thread (14 rows / 2)
#define NTHR  512    // 16 warps -> 4 per SMSP
#define GRID  147    // ceil(2048/14)
#define KCH   8      // k-chunk (2 x LDG.128 weight prefetch per chunk)

typedef unsigned long long u64;

// Transposed + 4k-packed weight scratch: element (k,n) at [(k>>2)*2048 + n*4 + (k&3)].
// Thread n loads float4 = weights for 4 consecutive k at its n. Coalesced LDG.128.
__device__ float g_eT[HID * HID];
__device__ float g_dT[HID * HID];

__device__ __forceinline__ u64 bcast2(float v) {
    u64 r;
    asm("mov.b64 %0, {%1, %1};" : "=l"(r) : "r"(__float_as_uint(v)));
    return r;
}
__device__ __forceinline__ u64 pack2(float lo, float hi) {
    u64 r;
    asm("mov.b64 %0, {%1, %2};" : "=l"(r) : "r"(__float_as_uint(lo)), "r"(__float_as_uint(hi)));
    return r;
}
__device__ __forceinline__ u64 ffma2(u64 a, u64 b, u64 c) {
    u64 d;
    asm("fma.rn.f32x2 %0, %1, %2, %3;" : "=l"(d) : "l"(a), "l"(b), "l"(c));
    return d;
}
__device__ __forceinline__ u64 fadd2(u64 a, u64 b) {
    u64 d;
    asm("add.rn.f32x2 %0, %1, %2;" : "=l"(d) : "l"(a), "l"(b));
    return d;
}
__device__ __forceinline__ void unpack2(u64 v, float& lo, float& hi) {
    unsigned a, b;
    asm("mov.b64 {%0, %1}, %2;" : "=r"(a), "=r"(b) : "l"(v));
    lo = __uint_as_float(a);
    hi = __uint_as_float(b);
}

// Transpose + pack both 512x512 matrices into g_eT/g_dT.
__global__ void transpose_both(const float* __restrict__ eW, const float* __restrict__ dW) {
    __shared__ float tile[32][33];   // tile[n_local][k_local]
    const float* src = blockIdx.z ? dW : eW;
    float* dst = blockIdx.z ? g_dT : g_eT;
    int k0 = blockIdx.x * 32;
    int n0 = blockIdx.y * 32;
    int tx = threadIdx.x, ty = threadIdx.y;
    #pragma unroll
    for (int i = 0; i < 32; i += 8)
        tile[ty + i][tx] = src[(n0 + ty + i) * HID + (k0 + tx)];   // coalesced read
    __syncthreads();
    // thread (tx=n_local, ty=k_group 0..7) writes float4 of 4 consecutive k
    float4* dst4 = (float4*)dst;
    #pragma unroll 1
    for (int g = ty; g < 8; g += 8) {
        float4 v = make_float4(tile[tx][4*g + 0], tile[tx][4*g + 1],
                               tile[tx][4*g + 2], tile[tx][4*g + 3]);
        dst4[((k0 >> 2) + g) * HID + (n0 + tx)] = v;               // coalesced write
    }
}

__global__ __launch_bounds__(NTHR, 1)
void rnn_kernel(const float* __restrict__ x,
                const float* __restrict__ eWih,
                const float* __restrict__ ebih, const float* __restrict__ ebhh,
                const float* __restrict__ dWih,
                const float* __restrict__ dbih, const float* __restrict__ dbhh,
                const float* __restrict__ fcW, const float* __restrict__ fcb,
                float* __restrict__ out)
{
    // Double-buffered h state: k-major, padded to 16 floats per hidden index.
    __shared__ __align__(16) float h0buf[HID][MRP];   // 32 KB
    __shared__ __align__(16) float h1buf[HID][MRP];   // 32 KB
    __shared__ __align__(16) float xs[SEQ][MRP];      // 8 KB
    __shared__ __align__(16) float dinp[MRP];
    __shared__ float red[4][MRP];

    const int tid = threadIdx.x;           // == this thread's hidden unit n
    const int b0 = blockIdx.x * MR;
    const int rows = min(MR, BATCH - b0);

    // h0 = 0
    for (int i = tid; i < HID * MRP / 4; i += NTHR)
        ((float4*)h0buf)[i] = make_float4(0.f, 0.f, 0.f, 0.f);
    // xs[s][m] = x[(b0+m)*SEQ + s], coalesced along s; zero OOB/pad rows.
    for (int i = tid; i < MRP * SEQ; i += NTHR) {
        int m = i >> 7;           // SEQ == 128
        int s = i & (SEQ - 1);
        xs[s][m] = (m < rows) ? x[(b0 + m) * SEQ + s] : 0.f;
    }

    // Per-thread constants for this hidden unit.
    const float wihE = eWih[tid];
    const float biasE = ebih[tid] + ebhh[tid];
    const float wihD = dWih[tid];
    const float biasD = dbih[tid] + dbhh[tid];
    const float fcb0 = fcb[0];

    __syncthreads();

    // One recurrent step: dst = tanh(inp*wih + bias + src @ Whh^T). One barrier.
    auto step = [&](const float* __restrict__ Wt, const float wih, const float bias,
                    const float* __restrict__ inp,
                    const float (*__restrict__ src)[MRP], float (*__restrict__ dst)[MRP]) {
        u64 acc[NACC];
        #pragma unroll
        for (int p = 0; p < NACC; p++) acc[p] = 0ULL;

        const float4* wp = (const float4*)Wt + tid;   // [(k>>2)*512 + tid]
        float4 wc0 = wp[0];
        float4 wc1 = wp[HID];

        #pragma unroll 1
        for (int k0 = 0; k0 < HID; k0 += KCH) {
            const int g2 = ((k0 + KCH) & (HID - 1)) >> 2;      // depth-1 prefetch
            float4 wn0 = wp[g2 * HID];
            float4 wn1 = wp[(g2 + 1) * HID];

            const float wv[KCH] = {wc0.x, wc0.y, wc0.z, wc0.w,
                                   wc1.x, wc1.y, wc1.z, wc1.w};
            #pragma unroll
            for (int j = 0; j < KCH; j++) {
                const u64 wb = bcast2(wv[j]);
                const u64* hp = (const u64*)&src[k0 + j][0];   // warp-broadcast LDS
                ulonglong2 v0 = ((const ulonglong2*)hp)[0];
                ulonglong2 v1 = ((const ulonglong2*)hp)[1];
                ulonglong2 v2 = ((const ulonglong2*)hp)[2];
                u64 v3 = hp[6];
                acc[0] = ffma2(v0.x, wb, acc[0]);
                acc[1] = ffma2(v0.y, wb, acc[1]);
                acc[2] = ffma2(v1.x, wb, acc[2]);
                acc[3] = ffma2(v1.y, wb, acc[3]);
                acc[4] = ffma2(v2.x, wb, acc[4]);
                acc[5] = ffma2(v2.y, wb, acc[5]);
                acc[6] = ffma2(v3,   wb, acc[6]);
            }
            wc0 = wn0;
            wc1 = wn1;
        }

        // epilogue: input term + bias + tanh -> dst row for this hidden unit
        const u64 wb = bcast2(wih);
        const u64 bb = bcast2(bias);
        const u64* xp = (const u64*)inp;
        u64* drow = (u64*)&dst[tid][0];
        #pragma unroll
        for (int p = 0; p < NACC; p++) {
            u64 v = ffma2(xp[p], wb, fadd2(acc[p], bb));
            float lo, hi;
            unpack2(v, lo, hi);
            drow[p] = pack2(tanhf(lo), tanhf(hi));
        }
        __syncthreads();   // writes to dst visible; reads of src complete
    };

    // fc head over given buffer; writes out column t and dinp feedback.
    auto fchead = [&](const float (*__restrict__ hb)[MRP], int t) {
        if (tid < 64) {
            const int m = tid & (MRP - 1);
            const int sl = tid >> 4;
            float s = 0.f;
            const float* fw = fcW + sl * 128;
            #pragma unroll 4
            for (int k = 0; k < 128; k++)
                s = fmaf(hb[sl * 128 + k][m], fw[k], s);
            red[sl][m] = s;
        }
        __syncthreads();
        if (tid < MR) {
            float o = red[0][tid] + red[1][tid] + red[2][tid] + red[3][tid] + fcb0;
            dinp[tid] = o;
            if (b0 + tid < BATCH) out[(b0 + tid) * TOUT + t] = o;
        }
        __syncthreads();
    };

    // ---- encoder: 128 steps, ping-pong buffers (even count -> ends in h0buf) ----
    #pragma unroll 1
    for (int t = 0; t < SEQ; t += 2) {
        step(g_eT, wihE, biasE, &xs[t][0],     h0buf, h1buf);
        step(g_eT, wihE, biasE, &xs[t + 1][0], h1buf, h0buf);
    }

    // ---- decoder: 24 steps with fc head + feedback ----
    if (tid < MRP) dinp[tid] = xs[SEQ - 1][tid];
    __syncthreads();

    #pragma unroll 1
    for (int t = 0; t < TOUT; t += 2) {
        step(g_dT, wihD, biasD, dinp, h0buf, h1buf);
        fchead(h1buf, t);
        step(g_dT, wihD, biasD, dinp, h1buf, h0buf);
        fchead(h0buf, t + 1);
    }
}

extern "C" void kernel_launch(void* const* d_in, const int* in_sizes, int n_in,
                              void* d_out, int out_size) {
    (void)in_sizes; (void)n_in; (void)out_size;
    const float* x    = (const float*)d_in[0];
    const float* eWih = (const float*)d_in[1];
    const float* eWhh = (const float*)d_in[2];
    const float* ebih = (const float*)d_in[3];
    const float* ebhh = (const float*)d_in[4];
    const float* dWih = (const float*)d_in[5];
    const float* dWhh = (const float*)d_in[6];
    const float* dbih = (const float*)d_in[7];
    const float* dbhh = (const float*)d_in[8];
    const float* fcW  = (const float*)d_in[9];
    const float* fcb  = (const float*)d_in[10];

    dim3 tgrid(HID / 32, HID / 32, 2);
    dim3 tblk(32, 8, 1);
    transpose_both<<<tgrid, tblk>>>(eWhh, dWhh);

    rnn_kernel<<<GRID, NTHR>>>(x, eWih, ebih, ebhh,
                               dWih, dbih, dbhh,
                               fcW, fcb, (float*)d_out);
}

// round 7
// speedup vs baseline: 1.2742x; 1.2742x over previous
#include <cuda_runtime.h>
#include <math.h>

#define BATCH 2048
#define SEQ   128
#define HID   512
#define TOUT  24
#define MR    16     // batch rows per CTA
#define HPAD  20     // padded h row (floats): 80B, 16B-aligned, kills STS conflicts
#define NTHR  512    // 16 warps -> 4 per SMSP; split-K halves
#define GRID  128
#define KCH   4      // k per prefetch chunk
#define KHALF 256    // k range per warp-group
#define NCHH  (KHALF / KCH)   // 64 chunks per half

typedef unsigned long long u64;

// Transposed (k-major) weights: g_T[k*512 + n] = W[n*512 + k].
__device__ float g_eT[HID * HID];
__device__ float g_dT[HID * HID];

__device__ __forceinline__ u64 bcast2(float v) {
    u64 r;
    asm("mov.b64 %0, {%1, %1};" : "=l"(r) : "r"(__float_as_uint(v)));
    return r;
}
__device__ __forceinline__ u64 pack2(float lo, float hi) {
    u64 r;
    asm("mov.b64 %0, {%1, %2};" : "=l"(r) : "r"(__float_as_uint(lo)), "r"(__float_as_uint(hi)));
    return r;
}
__device__ __forceinline__ u64 ffma2(u64 a, u64 b, u64 c) {
    u64 d;
    asm("fma.rn.f32x2 %0, %1, %2, %3;" : "=l"(d) : "l"(a), "l"(b), "l"(c));
    return d;
}
__device__ __forceinline__ u64 fadd2(u64 a, u64 b) {
    u64 d;
    asm("add.rn.f32x2 %0, %1, %2;" : "=l"(d) : "l"(a), "l"(b));
    return d;
}
__device__ __forceinline__ void unpack2(u64 v, float& lo, float& hi) {
    unsigned a, b;
    asm("mov.b64 {%0, %1}, %2;" : "=r"(a), "=r"(b) : "l"(v));
    lo = __uint_as_float(a);
    hi = __uint_as_float(b);
}

// Transpose both 512x512 recurrent matrices (coalesced both sides).
__global__ void transpose_both(const float* __restrict__ eW, const float* __restrict__ dW) {
    __shared__ float tile[32][33];
    const float* src = blockIdx.z ? dW : eW;
    float* dst = blockIdx.z ? g_dT : g_eT;
    int k = blockIdx.x * 32 + threadIdx.x;
    int n = blockIdx.y * 32 + threadIdx.y;
    #pragma unroll
    for (int i = 0; i < 32; i += 8)
        tile[threadIdx.y + i][threadIdx.x] = src[(n + i) * HID + k];
    __syncthreads();
    int n2 = blockIdx.y * 32 + threadIdx.x;
    int k2 = blockIdx.x * 32 + threadIdx.y;
    #pragma unroll
    for (int i = 0; i < 32; i += 8)
        dst[(k2 + i) * HID + n2] = tile[threadIdx.x][threadIdx.y + i];
}

// Dynamic SMEM layout (bytes)
#define OFF_H    0                       // h[512][20] floats   = 40960
#define OFF_XS   40960                   // xs[128][16] floats  = 8192
#define OFF_XCH  49152                   // xch: 512 * 10 u64   = 40960 (80B stride, 16B aligned)
#define OFF_DINP 90112                   // 16 floats
#define OFF_RED  90176                   // 4*16 floats
#define SMEM_SZ  90448

__global__ __launch_bounds__(NTHR, 1)
void rnn_kernel(const float* __restrict__ x,
                const float* __restrict__ eWih,
                const float* __restrict__ ebih, const float* __restrict__ ebhh,
                const float* __restrict__ dWih,
                const float* __restrict__ dbih, const float* __restrict__ dbhh,
                const float* __restrict__ fcW, const float* __restrict__ fcb,
                float* __restrict__ out)
{
    extern __shared__ char smem[];
    float (*h)[HPAD]  = (float (*)[HPAD])(smem + OFF_H);
    float (*xs)[MR]   = (float (*)[MR])(smem + OFF_XS);
    u64*  xch         = (u64*)(smem + OFF_XCH);
    float* dinp       = (float*)(smem + OFF_DINP);
    float (*red)[MR]  = (float (*)[MR])(smem + OFF_RED);

    const int tid   = threadIdx.x;
    const int khalf = tid >> 8;          // 0: k in [0,256), 1: [256,512)
    const int nh    = tid & 255;         // float2 index into weight row
    const int ncol  = nh * 2 + khalf;    // hidden column this thread finalizes
    const int kbase = khalf * KHALF;
    const int b0    = blockIdx.x * MR;

    // h0 = 0 (including pad)
    for (int i = tid; i < HID * HPAD / 4; i += NTHR)
        ((float4*)(smem + OFF_H))[i] = make_float4(0.f, 0.f, 0.f, 0.f);
    // xs[s][m] = x[(b0+m)*SEQ + s] (coalesced along s)
    for (int i = tid; i < MR * SEQ; i += NTHR) {
        int m = i >> 7, s = i & (SEQ - 1);
        xs[s][m] = x[(b0 + m) * SEQ + s];
    }

    // Per-thread constants for the column it finalizes.
    const float wihE  = eWih[ncol];
    const float biasE = ebih[ncol] + ebhh[ncol];
    const float wihD  = dWih[ncol];
    const float biasD = dbih[ncol] + dbhh[ncol];
    const float fcb0  = fcb[0];

    __syncthreads();

    // One recurrent step. Split-K: each warp-group accumulates its k-half for
    // BOTH of the thread's two columns, then the halves are exchanged via SMEM
    // so each thread finalizes exactly one column (tanh + h write).
    auto step = [&](const float* __restrict__ Wt, const float wih, const float bias,
                    const float* __restrict__ inp) {
        u64 acc[2][8];
        #pragma unroll
        for (int n = 0; n < 2; n++)
            #pragma unroll
            for (int p = 0; p < 8; p++) acc[n][p] = 0ULL;

        const float2* wp = (const float2*)Wt + nh;   // Wt[k*512 + 2*nh] as float2
        float2 wc[KCH], wn[KCH];
        #pragma unroll
        for (int j = 0; j < KCH; j++) wc[j] = wp[(kbase + j) * (HID / 2)];

        #pragma unroll 1
        for (int c = 0; c < NCHH; c++) {
            const int kc = kbase + c * KCH;
            const int kn = kbase + ((c + 1) & (NCHH - 1)) * KCH;  // depth-1 prefetch
            #pragma unroll
            for (int j = 0; j < KCH; j++) wn[j] = wp[(kn + j) * (HID / 2)];

            #pragma unroll
            for (int j = 0; j < KCH; j++) {
                const u64 w0 = bcast2(wc[j].x);
                const u64 w1 = bcast2(wc[j].y);
                const ulonglong2* hp = (const ulonglong2*)&h[kc + j][0]; // broadcast LDS
                #pragma unroll
                for (int q = 0; q < 4; q++) {
                    ulonglong2 hv = hp[q];
                    acc[0][2*q]   = ffma2(hv.x, w0, acc[0][2*q]);
                    acc[0][2*q+1] = ffma2(hv.y, w0, acc[0][2*q+1]);
                    acc[1][2*q]   = ffma2(hv.x, w1, acc[1][2*q]);
                    acc[1][2*q+1] = ffma2(hv.y, w1, acc[1][2*q+1]);
                }
            }
            #pragma unroll
            for (int j = 0; j < KCH; j++) wc[j] = wn[j];
        }

        // Exchange the non-owned column's partials (64B per thread, 80B stride
        // -> conflict-free STS/LDS.128).
        const int own = khalf;           // khalf0 owns even col (acc[0]), khalf1 odd (acc[1])
        ulonglong2* sv = (ulonglong2*)(xch + tid * 10);
        #pragma unroll
        for (int q = 0; q < 4; q++)
            sv[q] = make_ulonglong2(acc[1 - own][2*q], acc[1 - own][2*q + 1]);
        __syncthreads();                 // also proves: ALL h reads of this step are done

        const ulonglong2* pv = (const ulonglong2*)(xch + (tid ^ 256) * 10);
        const u64 wb = bcast2(wih);
        const u64 bb = bcast2(bias);
        const u64* xp = (const u64*)inp;
        ulonglong2 hout[4];
        #pragma unroll
        for (int q = 0; q < 4; q++) {
            ulonglong2 pr = pv[q];
            u64 m0 = fadd2(acc[own][2*q],     pr.x);
            u64 m1 = fadd2(acc[own][2*q + 1], pr.y);
            u64 v0 = ffma2(xp[2*q],     wb, fadd2(m0, bb));
            u64 v1 = ffma2(xp[2*q + 1], wb, fadd2(m1, bb));
            float a, b;
            unpack2(v0, a, b); hout[q].x = pack2(tanhf(a), tanhf(b));
            unpack2(v1, a, b); hout[q].y = pack2(tanhf(a), tanhf(b));
        }
        ulonglong2* hw = (ulonglong2*)&h[ncol][0];   // in-place: safe (all reads done)
        #pragma unroll
        for (int q = 0; q < 4; q++) hw[q] = hout[q];
        __syncthreads();                 // new h visible
    };

    // ---- encoder: 128 steps (step 0 runs over h=0, which is exact) ----
    #pragma unroll 1
    for (int t = 0; t < SEQ; t++)
        step(g_eT, wihE, biasE, &xs[t][0]);

    // ---- decoder: 24 steps with fc head + feedback ----
    if (tid < MR) dinp[tid] = xs[SEQ - 1][tid];
    __syncthreads();

    #pragma unroll 1
    for (int t = 0; t < TOUT; t++) {
        step(g_dT, wihD, biasD, dinp);

        // fc: out[m] = sum_k h[k][m] * fcW[k] + fcb
        if (tid < 64) {
            const int m = tid & (MR - 1);
            const int sl = tid >> 4;
            float s = 0.f;
            const float* fw = fcW + sl * 128;
            #pragma unroll 4
            for (int k = 0; k < 128; k++)
                s = fmaf(h[sl * 128 + k][m], fw[k], s);
            red[sl][m] = s;
        }
        __syncthreads();
        if (tid < MR) {
            float o = red[0][tid] + red[1][tid] + red[2][tid] + red[3][tid] + fcb0;
            dinp[tid] = o;
            out[(b0 + tid) * TOUT + t] = o;
        }
        __syncthreads();
    }
}

extern "C" void kernel_launch(void* const* d_in, const int* in_sizes, int n_in,
                              void* d_out, int out_size) {
    (void)in_sizes; (void)n_in; (void)out_size;
    const float* x    = (const float*)d_in[0];
    const float* eWih = (const float*)d_in[1];
    const float* eWhh = (const float*)d_in[2];
    const float* ebih = (const float*)d_in[3];
    const float* ebhh = (const float*)d_in[4];
    const float* dWih = (const float*)d_in[5];
    const float* dWhh = (const float*)d_in[6];
    const float* dbih = (const float*)d_in[7];
    const float* dbhh = (const float*)d_in[8];
    const float* fcW  = (const float*)d_in[9];
    const float* fcb  = (const float*)d_in[10];

    cudaFuncSetAttribute(rnn_kernel, cudaFuncAttributeMaxDynamicSharedMemorySize, SMEM_SZ);

    dim3 tgrid(HID / 32, HID / 32, 2);
    dim3 tblk(32, 8, 1);
    transpose_both<<<tgrid, tblk>>>(eWhh, dWhh);

    rnn_kernel<<<GRID, NTHR, SMEM_SZ>>>(x, eWih, ebih, ebhh,
                                        dWih, dbih, dbhh,
                                        fcW, fcb, (float*)d_out);
}

// round 8
// speedup vs baseline: 1.3040x; 1.0234x over previous
#include <cuda_runtime.h>
#include <math.h>
#include <stdint.h>

#define BATCH 2048
#define SEQ   128
#define HID   512
#define TOUT  24
#define MR    16     // batch rows per CTA
#define HPAD  20     // padded h row (floats)
#define NTHR  512    // 16 warps -> 4/SMSP; 2 warp-groups split K
#define GRID  128
#define KCH   4      // k per chunk
#define NCHH  64     // chunks per k-half (256/4)

typedef unsigned long long u64;

// Transposed (k-major) weights: g_T[k*512 + n] = W[n*512 + k].
__device__ float g_eT[HID * HID];
__device__ float g_dT[HID * HID];

__device__ __forceinline__ u64 bcast2(float v) {
    u64 r;
    asm("mov.b64 %0, {%1, %1};" : "=l"(r) : "r"(__float_as_uint(v)));
    return r;
}
__device__ __forceinline__ u64 pack2(float lo, float hi) {
    u64 r;
    asm("mov.b64 %0, {%1, %2};" : "=l"(r) : "r"(__float_as_uint(lo)), "r"(__float_as_uint(hi)));
    return r;
}
__device__ __forceinline__ u64 ffma2(u64 a, u64 b, u64 c) {
    u64 d;
    asm("fma.rn.f32x2 %0, %1, %2, %3;" : "=l"(d) : "l"(a), "l"(b), "l"(c));
    return d;
}
__device__ __forceinline__ u64 fadd2(u64 a, u64 b) {
    u64 d;
    asm("add.rn.f32x2 %0, %1, %2;" : "=l"(d) : "l"(a), "l"(b));
    return d;
}
__device__ __forceinline__ void unpack2(u64 v, float& lo, float& hi) {
    unsigned a, b;
    asm("mov.b64 {%0, %1}, %2;" : "=r"(a), "=r"(b) : "l"(v));
    lo = __uint_as_float(a);
    hi = __uint_as_float(b);
}
__device__ __forceinline__ void cpasync16(uint32_t dst, const void* src) {
    asm volatile("cp.async.cg.shared.global [%0], [%1], 16;" :: "r"(dst), "l"(src) : "memory");
}
__device__ __forceinline__ void cp_commit() {
    asm volatile("cp.async.commit_group;" ::: "memory");
}
__device__ __forceinline__ void cp_wait3() {
    asm volatile("cp.async.wait_group 3;" ::: "memory");
}
__device__ __forceinline__ void cp_wait0() {
    asm volatile("cp.async.wait_group 0;" ::: "memory");
}
__device__ __forceinline__ uint32_t smem_u32(const void* p) {
    uint32_t a;
    asm("{ .reg .u64 t; cvta.to.shared.u64 t, %1; cvt.u32.u64 %0, t; }" : "=r"(a) : "l"(p));
    return a;
}

// Transpose both 512x512 recurrent matrices (coalesced both sides).
__global__ void transpose_both(const float* __restrict__ eW, const float* __restrict__ dW) {
    __shared__ float tile[32][33];
    const float* src = blockIdx.z ? dW : eW;
    float* dst = blockIdx.z ? g_dT : g_eT;
    int k = blockIdx.x * 32 + threadIdx.x;
    int n = blockIdx.y * 32 + threadIdx.y;
    #pragma unroll
    for (int i = 0; i < 32; i += 8)
        tile[threadIdx.y + i][threadIdx.x] = src[(n + i) * HID + k];
    __syncthreads();
    int n2 = blockIdx.y * 32 + threadIdx.x;
    int k2 = blockIdx.x * 32 + threadIdx.y;
    #pragma unroll
    for (int i = 0; i < 32; i += 8)
        dst[(k2 + i) * HID + n2] = tile[threadIdx.x][threadIdx.y + i];
}

// Dynamic SMEM layout (bytes)
#define OFF_H    0                       // h[512][20] floats         = 40960
#define OFF_XS   40960                   // xs[128][16] floats        = 8192
#define OFF_XCH  49152                   // exchange: 512 * 80B       = 40960
#define OFF_DINP 90112                   // 16 floats
#define OFF_RED  90176                   // 4*16 floats + pad
#define OFF_WST  90624                   // 16 warps * 4 bufs * 1KB   = 65536
#define SMEM_SZ  156160

__global__ __launch_bounds__(NTHR, 1)
void rnn_kernel(const float* __restrict__ x,
                const float* __restrict__ eWih,
                const float* __restrict__ ebih, const float* __restrict__ ebhh,
                const float* __restrict__ dWih,
                const float* __restrict__ dbih, const float* __restrict__ dbhh,
                const float* __restrict__ fcW, const float* __restrict__ fcb,
                float* __restrict__ out)
{
    extern __shared__ char smem[];
    float (*h)[HPAD]  = (float (*)[HPAD])(smem + OFF_H);
    float (*xs)[MR]   = (float (*)[MR])(smem + OFF_XS);
    u64*  xch         = (u64*)(smem + OFF_XCH);
    float* dinp       = (float*)(smem + OFF_DINP);
    float (*red)[MR]  = (float (*)[MR])(smem + OFF_RED);

    const int tid   = threadIdx.x;
    const int wid   = tid >> 5, lane = tid & 31;
    const int khalf = tid >> 8;          // warp-group: 0 -> k[0,256), 1 -> k[256,512)
    const int nh    = tid & 255;         // float2 col-pair index (cols 2nh, 2nh+1)
    const int ncol  = nh * 2 + khalf;    // column this thread finalizes
    const int kbase = khalf * 256;
    const int wg    = wid & 7;           // warp index within its k-half group
    const int colb  = wg * 64;           // 64-column window this warp stages
    const int b0    = blockIdx.x * MR;

    // Warp-private staging ring: 4 bufs x 1KB (4 k-rows x 64 cols).
    float* wst = (float*)(smem + OFF_WST + wid * 4096);
    const uint32_t wst_u = smem_u32(wst);
    // staging address components for this thread (2 x 16B per chunk)
    const int st_row = lane >> 4;        // 0..1 (instr covers 2 k-rows)
    const int st_col = (lane & 15) * 4;  // 16 floats per row segment

    // h0 = 0
    for (int i = tid; i < HID * HPAD / 4; i += NTHR)
        ((float4*)(smem + OFF_H))[i] = make_float4(0.f, 0.f, 0.f, 0.f);
    // xs[s][m] = x[(b0+m)*SEQ + s]
    for (int i = tid; i < MR * SEQ; i += NTHR) {
        int m = i >> 7, s = i & (SEQ - 1);
        xs[s][m] = x[(b0 + m) * SEQ + s];
    }

    const float wihE  = eWih[ncol];
    const float biasE = ebih[ncol] + ebhh[ncol];
    const float wihD  = dWih[ncol];
    const float biasD = dbih[ncol] + dbhh[ncol];
    const float fcb0  = fcb[0];

    __syncthreads();

    // Stage chunk c of matrix Wt into ring buffer (c&3). Warp-local; 2x cp.async 16B.
    auto stage = [&](const float* __restrict__ Wt, int c) {
        const int k0 = kbase + c * KCH;
        const float* s0 = Wt + (k0 + st_row) * HID + colb + st_col;
        uint32_t d0 = wst_u + (c & 3) * 1024 + st_row * 256 + (lane & 15) * 16;
        cpasync16(d0, s0);
        cpasync16(d0 + 512, s0 + 2 * HID);
        cp_commit();
    };
    // Prime: stage chunks 0..2.
    auto prime = [&](const float* __restrict__ Wt) {
        stage(Wt, 0);
        stage(Wt, 1);
        stage(Wt, 2);
    };

    // One recurrent step. Weight pipeline: depth-4 cp.async ring, wraps mod 64
    // (same matrix next step, so cross-step latency also hidden).
    auto step = [&](const float* __restrict__ Wt, const float wih, const float bias,
                    const float* __restrict__ inp) {
        u64 acc[2][8];
        #pragma unroll
        for (int n = 0; n < 2; n++)
            #pragma unroll
            for (int p = 0; p < 8; p++) acc[n][p] = 0ULL;

        #pragma unroll 1
        for (int c = 0; c < NCHH; c++) {
            stage(Wt, (c + 3) & (NCHH - 1));
            cp_wait3();                              // chunk c's buffer ready
            const float* wb_ = wst + (c & 3) * 256;  // [4 k][64 cols]
            const int kc = kbase + c * KCH;
            #pragma unroll
            for (int j = 0; j < KCH; j++) {
                const float2 w = *(const float2*)(wb_ + j * 64 + lane * 2); // conflict-free LDS.64
                const u64 w0 = bcast2(w.x);
                const u64 w1 = bcast2(w.y);
                const ulonglong2* hp = (const ulonglong2*)&h[kc + j][0];    // broadcast LDS
                #pragma unroll
                for (int q = 0; q < 4; q++) {
                    ulonglong2 hv = hp[q];
                    acc[0][2*q]   = ffma2(hv.x, w0, acc[0][2*q]);
                    acc[0][2*q+1] = ffma2(hv.y, w0, acc[0][2*q+1]);
                    acc[1][2*q]   = ffma2(hv.x, w1, acc[1][2*q]);
                    acc[1][2*q+1] = ffma2(hv.y, w1, acc[1][2*q+1]);
                }
            }
        }

        // Exchange the non-owned column's partials (64B/thread, 80B stride).
        const int own = khalf;
        ulonglong2* sv = (ulonglong2*)(xch + tid * 10);
        #pragma unroll
        for (int q = 0; q < 4; q++)
            sv[q] = make_ulonglong2(acc[1 - own][2*q], acc[1 - own][2*q + 1]);
        __syncthreads();                 // also proves all h reads of this step done

        const ulonglong2* pv = (const ulonglong2*)(xch + (tid ^ 256) * 10);
        const u64 wb = bcast2(wih);
        const u64 bb = bcast2(bias);
        const u64* xp = (const u64*)inp;
        ulonglong2 hout[4];
        #pragma unroll
        for (int q = 0; q < 4; q++) {
            ulonglong2 pr = pv[q];
            u64 m0 = fadd2(acc[own][2*q],     pr.x);
            u64 m1 = fadd2(acc[own][2*q + 1], pr.y);
            u64 v0 = ffma2(xp[2*q],     wb, fadd2(m0, bb));
            u64 v1 = ffma2(xp[2*q + 1], wb, fadd2(m1, bb));
            float a, b;
            unpack2(v0, a, b); hout[q].x = pack2(tanhf(a), tanhf(b));
            unpack2(v1, a, b); hout[q].y = pack2(tanhf(a), tanhf(b));
        }
        ulonglong2* hw = (ulonglong2*)&h[ncol][0];   // in-place: safe (reads done)
        #pragma unroll
        for (int q = 0; q < 4; q++) hw[q] = hout[q];
        __syncthreads();                 // new h visible
    };

    // ---- encoder: 128 steps, continuous weight pipeline ----
    prime(g_eT);
    #pragma unroll 1
    for (int t = 0; t < SEQ; t++)
        step(g_eT, wihE, biasE, &xs[t][0]);

    // ---- drain & re-prime for decoder weights ----
    cp_wait0();
    prime(g_dT);

    if (tid < MR) dinp[tid] = xs[SEQ - 1][tid];
    __syncthreads();

    #pragma unroll 1
    for (int t = 0; t < TOUT; t++) {
        step(g_dT, wihD, biasD, dinp);

        // fc: out[m] = sum_k h[k][m] * fcW[k] + fcb
        if (tid < 64) {
            const int m = tid & (MR - 1);
            const int sl = tid >> 4;
            float s = 0.f;
            const float* fw = fcW + sl * 128;
            #pragma unroll 4
            for (int k = 0; k < 128; k++)
                s = fmaf(h[sl * 128 + k][m], fw[k], s);
            red[sl][m] = s;
        }
        __syncthreads();
        if (tid < MR) {
            float o = red[0][tid] + red[1][tid] + red[2][tid] + red[3][tid] + fcb0;
            dinp[tid] = o;
            out[(b0 + tid) * TOUT + t] = o;
        }
        __syncthreads();
    }
}

extern "C" void kernel_launch(void* const* d_in, const int* in_sizes, int n_in,
                              void* d_out, int out_size) {
    (void)in_sizes; (void)n_in; (void)out_size;
    const float* x    = (const float*)d_in[0];
    const float* eWih = (const float*)d_in[1];
    const float* eWhh = (const float*)d_in[2];
    const float* ebih = (const float*)d_in[3];
    const float* ebhh = (const float*)d_in[4];
    const float* dWih = (const float*)d_in[5];
    const float* dWhh = (const float*)d_in[6];
    const float* dbih = (const float*)d_in[7];
    const float* dbhh = (const float*)d_in[8];
    const float* fcW  = (const float*)d_in[9];
    const float* fcb  = (const float*)d_in[10];

    cudaFuncSetAttribute(rnn_kernel, cudaFuncAttributeMaxDynamicSharedMemorySize, SMEM_SZ);

    dim3 tgrid(HID / 32, HID / 32, 2);
    dim3 tblk(32, 8, 1);
    transpose_both<<<tgrid, tblk>>>(eWhh, dWhh);

    rnn_kernel<<<GRID, NTHR, SMEM_SZ>>>(x, eWih, ebih, ebhh,
                                        dWih, dbih, dbhh,
                                        fcW, fcb, (float*)d_out);
}

// round 9
// speedup vs baseline: 3.0788x; 2.3610x over previous
#include <cuda_runtime.h>
#include <cuda_bf16.h>
#include <math.h>
#include <stdint.h>

#define BATCH 2048
#define SEQ   128
#define HID   512
#define TOUT  24
#define MR    16      // batch rows per CTA
#define NTHR  512     // 16 warps
#define GRID  128
#define NKT   32      // k-tiles of 16

// ---- SMEM layout (bytes) ----
#define OFF_A    0        // A planes: 2 bufs x 32 kt x 32 lanes x 32B = 65536
#define OFF_B    65536    // B ring: 16 warps x 4 bufs x 4 nt x 32 lanes x 16B = 131072
#define OFF_XS   196608   // xs[128][16] fp32 = 8192
#define OFF_EE   204800   // enc epilogue pack: 256 x float4 = 4096
#define OFF_ED   208896   // dec epilogue pack: 4096
#define OFF_FC   212992   // fc pairs: 256 x float2 = 2048
#define OFF_RED  215040   // 16 warps x 16 rows fp32 = 1024
#define OFF_DINP 216064   // 16 fp32
#define SMEM_SZ  216128

// Pre-packed B (Whh) in mma fragment order, bf16 hi/lo:
// entry e = ((kt*16 + w)*4 + ntl)*32 + lane -> uint4 {b0h, b1h, b0l, b1l}
__device__ uint4 g_eBpk[65536];
__device__ uint4 g_dBpk[65536];

__device__ __forceinline__ uint32_t smem_u32(const void* p) {
    uint32_t a;
    asm("{ .reg .u64 t; cvta.to.shared.u64 t, %1; cvt.u32.u64 %0, t; }" : "=r"(a) : "l"(p));
    return a;
}
__device__ __forceinline__ void cpasync16(uint32_t dst, const void* src) {
    asm volatile("cp.async.cg.shared.global [%0], [%1], 16;" :: "r"(dst), "l"(src) : "memory");
}
__device__ __forceinline__ void cp_commit() {
    asm volatile("cp.async.commit_group;" ::: "memory");
}
__device__ __forceinline__ void cp_wait3() {
    asm volatile("cp.async.wait_group 3;" ::: "memory");
}
__device__ __forceinline__ void cp_wait0() {
    asm volatile("cp.async.wait_group 0;" ::: "memory");
}
__device__ __forceinline__ void mma_bf16(float* d,
                                         uint32_t a0, uint32_t a1, uint32_t a2, uint32_t a3,
                                         uint32_t b0, uint32_t b1) {
    asm volatile(
        "mma.sync.aligned.m16n8k16.row.col.f32.bf16.bf16.f32 "
        "{%0,%1,%2,%3}, {%4,%5,%6,%7}, {%8,%9}, {%0,%1,%2,%3};"
        : "+f"(d[0]), "+f"(d[1]), "+f"(d[2]), "+f"(d[3])
        : "r"(a0), "r"(a1), "r"(a2), "r"(a3), "r"(b0), "r"(b1));
}
__device__ __forceinline__ uint32_t pack_bf2(__nv_bfloat16 a, __nv_bfloat16 b) {
    __nv_bfloat162 t;
    t.x = a; t.y = b;               // low half = first (smaller-k) element
    return *reinterpret_cast<uint32_t*>(&t);
}
// Split pair (a,b) -> hi bf16x2 + lo bf16x2 (residual): v = hi + lo to ~2^-18 rel.
__device__ __forceinline__ void split2(float a, float b, uint32_t& hi, uint32_t& lo) {
    __nv_bfloat16 ah = __float2bfloat16(a);
    __nv_bfloat16 bh = __float2bfloat16(b);
    __nv_bfloat16 al = __float2bfloat16(a - __bfloat162float(ah));
    __nv_bfloat16 bl = __float2bfloat16(b - __bfloat162float(bh));
    hi = pack_bf2(ah, bh);
    lo = pack_bf2(al, bl);
}

// Prologue: pack Whh (both matrices) into fragment-ordered bf16 hi/lo entries.
// Fragment (m16n8k16 row.col): n = w*32 + ntl*8 + (lane>>2), k = kt*16 + 2*(lane&3);
// b0 = {B[k][n], B[k+1][n]} = {W[n][k], W[n][k+1]}, b1 = same at k+8.
__global__ void pack_b(const float* __restrict__ eW, const float* __restrict__ dW) {
    int e = blockIdx.x * 256 + threadIdx.x;   // 0..65535
    const float* W = blockIdx.y ? dW : eW;
    uint4* dst = blockIdx.y ? g_dBpk : g_eBpk;
    int lane = e & 31;
    int ntl  = (e >> 5) & 3;
    int w    = (e >> 7) & 15;
    int kt   = e >> 11;
    int n = w * 32 + ntl * 8 + (lane >> 2);
    int k = kt * 16 + 2 * (lane & 3);
    const float* r = W + n * HID + k;
    uint32_t b0h, b0l, b1h, b1l;
    split2(r[0], r[1], b0h, b0l);
    split2(r[8], r[9], b1h, b1l);
    dst[e] = make_uint4(b0h, b1h, b0l, b1l);
}

__global__ __launch_bounds__(NTHR, 1)
void rnn_kernel(const float* __restrict__ x,
                const float* __restrict__ eWih,
                const float* __restrict__ ebih, const float* __restrict__ ebhh,
                const float* __restrict__ dWih,
                const float* __restrict__ dbih, const float* __restrict__ dbhh,
                const float* __restrict__ fcW, const float* __restrict__ fcb,
                float* __restrict__ out)
{
    extern __shared__ char smem[];
    const int tid  = threadIdx.x;
    const int wid  = tid >> 5, lane = tid & 31;
    const int gid  = lane >> 2, tig = lane & 3;   // fragment row group / col group
    const int b0   = blockIdx.x * MR;

    char*  smA   = smem + OFF_A;
    float* xs    = (float*)(smem + OFF_XS);       // [s][16]
    float4* epE  = (float4*)(smem + OFF_EE);
    float4* epD  = (float4*)(smem + OFF_ED);
    float2* fcp  = (float2*)(smem + OFF_FC);
    float* red   = (float*)(smem + OFF_RED);      // [w][16]
    float* dinp  = (float*)(smem + OFF_DINP);

    // ---- init: zero A buf0, load xs, build epilogue tables ----
    for (int i = tid; i < 2048; i += NTHR)        // 32768B = 2048 uint4
        ((uint4*)smA)[i] = make_uint4(0, 0, 0, 0);
    for (int i = tid; i < MR * SEQ; i += NTHR) {
        int m = i >> 7, s = i & (SEQ - 1);
        xs[s * MR + m] = x[(b0 + m) * SEQ + s];
    }
    for (int p = tid; p < 256; p += NTHR) {
        epE[p] = make_float4(eWih[2*p], eWih[2*p+1],
                             ebih[2*p] + ebhh[2*p], ebih[2*p+1] + ebhh[2*p+1]);
        epD[p] = make_float4(dWih[2*p], dWih[2*p+1],
                             dbih[2*p] + dbhh[2*p], dbih[2*p+1] + dbhh[2*p+1]);
        fcp[p] = make_float2(fcW[2*p], fcW[2*p+1]);
    }
    __syncthreads();

    const uint32_t bring_u = smem_u32(smem + OFF_B) + wid * 8192;
    const uint4*   bring   = (const uint4*)(smem + OFF_B) + wid * 512;
    const float    fcb0    = fcb[0];

    // Stage k-tile kt of packed B for this warp into ring buffer kt&3.
    // Each thread stages 4x16B and later reads exactly those bytes -> no syncs.
    auto stage = [&](const uint4* __restrict__ gB, int kt) {
        const uint4* src = gB + (kt * 16 + wid) * 128 + lane;
        uint32_t d = bring_u + (kt & 3) * 2048 + lane * 16;
        cpasync16(d,        src);
        cpasync16(d +  512, src + 32);
        cpasync16(d + 1024, src + 64);
        cpasync16(d + 1536, src + 96);
        cp_commit();
    };

    float acc[4][4];

    // K-loop: acc = Hprev @ Wslice^T via 3-term bf16 mma over 32 k-tiles.
    auto kloop = [&](const uint4* __restrict__ gB, int pb) {
        #pragma unroll
        for (int i = 0; i < 4; i++)
            #pragma unroll
            for (int j = 0; j < 4; j++) acc[i][j] = 0.f;

        const uint4* ap = (const uint4*)(smA + pb * 32768);
        #pragma unroll 1
        for (int kt = 0; kt < NKT; kt++) {
            stage(gB, (kt + 3) & (NKT - 1));
            cp_wait3();
            uint4 ah = ap[(kt * 32 + lane) * 2];        // {a0,a1,a2,a3} hi
            uint4 al = ap[(kt * 32 + lane) * 2 + 1];    // lo
            const uint4* bb = bring + (kt & 3) * 128 + lane;
            #pragma unroll
            for (int ntl = 0; ntl < 4; ntl++) {
                uint4 bq = bb[ntl * 32];                // {b0h,b1h,b0l,b1l}
                mma_bf16(acc[ntl], ah.x, ah.y, ah.z, ah.w, bq.x, bq.y);
                mma_bf16(acc[ntl], al.x, al.y, al.z, al.w, bq.x, bq.y);
                mma_bf16(acc[ntl], ah.x, ah.y, ah.z, ah.w, bq.z, bq.w);
            }
        }
    };

    // Epilogue: h = tanh(acc + xv*wih + bias); write next-step A planes (buf nb)
    // directly in fragment layout; optionally accumulate fc partials.
    auto epi = [&](const float* __restrict__ inp, const float4* __restrict__ ep,
                   int nb, bool dec) {
        float xv0 = inp[gid];
        float xv1 = inp[gid + 8];
        uint32_t hiP[2][4], loP[2][4];
        float s0 = 0.f, s1 = 0.f;
        #pragma unroll
        for (int i = 0; i < 4; i++) {
            int p = 16 * wid + 4 * i + tig;   // col-pair index (col = 2p)
            float4 co = ep[p];
            float h00 = tanhf(acc[i][0] + xv0 * co.x + co.z);
            float h01 = tanhf(acc[i][1] + xv0 * co.y + co.w);
            float h10 = tanhf(acc[i][2] + xv1 * co.x + co.z);
            float h11 = tanhf(acc[i][3] + xv1 * co.y + co.w);
            if (dec) {
                float2 f = fcp[p];
                s0 = fmaf(h00, f.x, fmaf(h01, f.y, s0));
                s1 = fmaf(h10, f.x, fmaf(h11, f.y, s1));
            }
            int half = i >> 1, sl = (i & 1) * 2;
            split2(h00, h01, hiP[half][sl],     loP[half][sl]);
            split2(h10, h11, hiP[half][sl + 1], loP[half][sl + 1]);
        }
        #pragma unroll
        for (int half = 0; half < 2; half++) {
            int kt = wid * 2 + half;
            uint4* w4 = (uint4*)(smA + nb * 32768 + (kt * 32 + lane) * 32);
            w4[0] = make_uint4(hiP[half][0], hiP[half][1], hiP[half][2], hiP[half][3]);
            w4[1] = make_uint4(loP[half][0], loP[half][1], loP[half][2], loP[half][3]);
        }
        if (dec) {
            s0 += __shfl_xor_sync(0xffffffffu, s0, 1);
            s0 += __shfl_xor_sync(0xffffffffu, s0, 2);
            s1 += __shfl_xor_sync(0xffffffffu, s1, 1);
            s1 += __shfl_xor_sync(0xffffffffu, s1, 2);
            if (tig == 0) {
                red[wid * 16 + gid]     = s0;
                red[wid * 16 + gid + 8] = s1;
            }
        }
    };

    // ---- encoder: 128 steps ----
    stage(g_eBpk, 0);
    stage(g_eBpk, 1);
    stage(g_eBpk, 2);
    int pb = 0;
    #pragma unroll 1
    for (int t = 0; t < SEQ; t++) {
        kloop(g_eBpk, pb);
        epi(xs + t * MR, epE, 1 - pb, false);
        __syncthreads();   // new A planes visible; also guards buffer flip
        pb ^= 1;
    }

    // ---- switch weights: drain ring, prime decoder ----
    cp_wait0();
    stage(g_dBpk, 0);
    stage(g_dBpk, 1);
    stage(g_dBpk, 2);
    if (tid < MR) dinp[tid] = xs[(SEQ - 1) * MR + tid];
    __syncthreads();

    // ---- decoder: 24 steps with fc head + feedback ----
    #pragma unroll 1
    for (int t = 0; t < TOUT; t++) {
        kloop(g_dBpk, pb);
        epi(dinp, epD, 1 - pb, true);
        __syncthreads();   // red + A planes visible
        if (tid < MR) {
            float o = fcb0;
            #pragma unroll
            for (int w2 = 0; w2 < 16; w2++) o += red[w2 * 16 + tid];
            dinp[tid] = o;
            out[(b0 + tid) * TOUT + t] = o;
        }
        __syncthreads();   // dinp stable before next epilogue reads it
        pb ^= 1;
    }
}

extern "C" void kernel_launch(void* const* d_in, const int* in_sizes, int n_in,
                              void* d_out, int out_size) {
    (void)in_sizes; (void)n_in; (void)out_size;
    const float* x    = (const float*)d_in[0];
    const float* eWih = (const float*)d_in[1];
    const float* eWhh = (const float*)d_in[2];
    const float* ebih = (const float*)d_in[3];
    const float* ebhh = (const float*)d_in[4];
    const float* dWih = (const float*)d_in[5];
    const float* dWhh = (const float*)d_in[6];
    const float* dbih = (const float*)d_in[7];
    const float* dbhh = (const float*)d_in[8];
    const float* fcW  = (const float*)d_in[9];
    const float* fcb  = (const float*)d_in[10];

    cudaFuncSetAttribute(rnn_kernel, cudaFuncAttributeMaxDynamicSharedMemorySize, SMEM_SZ);

    pack_b<<<dim3(256, 2), 256>>>(eWhh, dWhh);
    rnn_kernel<<<GRID, NTHR, SMEM_SZ>>>(x, eWih, ebih, ebhh,
                                        dWih, dbih, dbhh,
                                        fcW, fcb, (float*)d_out);
}